// round 2
// baseline (speedup 1.0000x reference)
#include <cuda_runtime.h>

// ---------------------------------------------------------------------------
// SelfAttentionBlock: graph attention with per-edge RPE.
// Shapes (fixed by problem): N=50000, E=800000, DIM=256, H=16, D=8, DH=128,
// IN_RPE=18. SCALE = 1/sqrt(8).
//
// Pipeline (5 kernels, single stream, graph-capturable, allocation-free):
//   K0 init     : zero d_out, zero g_sum, set g_max = -inf
//   K1 gemm     : g_qkv = x @ Wqkv + bqkv            (N, 512)
//   K2 compat   : per-edge RPE GEMVs + q.k dot, store compat, atomicMax
//   K3 expsum   : ex = exp(compat - max[s]), store ex, atomicAdd denom
//   K4 message  : out[s] += (ex/(den[s]+eps)) * v[t]   (scalar atomics)
//
// NOTE: edge_index arrives as int32 (JAX x64 disabled downgrades int64).
// ---------------------------------------------------------------------------

#define MAX_N 50000
#define MAX_E 800000
#define HH    16
#define SCALE 0.35355339059327373f   // 8^-0.5

// Scratch (device globals; allocation in kernel_launch is forbidden)
__device__ float g_qkv[(size_t)MAX_N * 512];   // [q(128) | k(128) | v(256)]
__device__ float g_ex [(size_t)MAX_E * HH];    // compat, then exp(compat-max)
__device__ float g_max[(size_t)MAX_N * HH];
__device__ float g_sum[(size_t)MAX_N * HH];

// ---------------------------------------------------------------------------
__device__ __forceinline__ void atomicMaxFloat(float* addr, float val) {
    // Standard bit-trick: works across mixed signs given -inf init.
    if (val >= 0.0f) {
        atomicMax((int*)addr, __float_as_int(val));
    } else {
        atomicMin((unsigned int*)addr, __float_as_uint(val));
    }
}

// --------------------------- K0: init --------------------------------------
__global__ void k_init(float* __restrict__ out, int n_out, int n_nodes) {
    int i = blockIdx.x * blockDim.x + threadIdx.x;
    if (i < n_out) out[i] = 0.0f;
    if (i < n_nodes * HH) {
        g_max[i] = __int_as_float(0xff800000);  // -inf
        g_sum[i] = 0.0f;
    }
}

// --------------------------- K1: qkv GEMM ----------------------------------
// C[M,512] = X[M,256] @ W[256,512] + bias ;  BM=128, BN=128, BK=8, TM=TN=8
__global__ void __launch_bounds__(256) k_gemm(
    const float* __restrict__ X, const float* __restrict__ W,
    const float* __restrict__ bias, int M)
{
    __shared__ float As[8][128];   // transposed A tile
    __shared__ float Bs[8][128];

    const int tid = threadIdx.x;
    const int tr  = tid >> 4;          // 0..15
    const int tc  = tid & 15;          // 0..15
    const int aRow = tid >> 1;         // 0..127
    const int aCol = (tid & 1) * 4;    // 0 or 4
    const int bRow = tid >> 5;         // 0..7
    const int bCol = (tid & 31) * 4;   // 0..124

    const int rowBase = blockIdx.y * 128;
    const int colBase = blockIdx.x * 128;
    const int gRow = rowBase + aRow;

    float acc[8][8];
#pragma unroll
    for (int i = 0; i < 8; i++)
#pragma unroll
        for (int j = 0; j < 8; j++) acc[i][j] = 0.0f;

    for (int k0 = 0; k0 < 256; k0 += 8) {
        float4 a4 = make_float4(0.f, 0.f, 0.f, 0.f);
        if (gRow < M)
            a4 = *(const float4*)(X + (size_t)gRow * 256 + k0 + aCol);
        As[aCol + 0][aRow] = a4.x;
        As[aCol + 1][aRow] = a4.y;
        As[aCol + 2][aRow] = a4.z;
        As[aCol + 3][aRow] = a4.w;

        *(float4*)&Bs[bRow][bCol] =
            *(const float4*)(W + (size_t)(k0 + bRow) * 512 + colBase + bCol);
        __syncthreads();

#pragma unroll
        for (int k = 0; k < 8; k++) {
            float4 a0 = *(float4*)&As[k][tr * 8];
            float4 a1 = *(float4*)&As[k][tr * 8 + 4];
            float4 b0 = *(float4*)&Bs[k][tc * 8];
            float4 b1 = *(float4*)&Bs[k][tc * 8 + 4];
            float ra[8] = {a0.x, a0.y, a0.z, a0.w, a1.x, a1.y, a1.z, a1.w};
            float rb[8] = {b0.x, b0.y, b0.z, b0.w, b1.x, b1.y, b1.z, b1.w};
#pragma unroll
            for (int i = 0; i < 8; i++)
#pragma unroll
                for (int j = 0; j < 8; j++)
                    acc[i][j] += ra[i] * rb[j];
        }
        __syncthreads();
    }

#pragma unroll
    for (int i = 0; i < 8; i++) {
        int row = rowBase + tr * 8 + i;
        if (row < M) {
            int col = colBase + tc * 8;
            float4 b0 = *(const float4*)(bias + col);
            float4 b1 = *(const float4*)(bias + col + 4);
            float4 o0 = make_float4(acc[i][0] + b0.x, acc[i][1] + b0.y,
                                    acc[i][2] + b0.z, acc[i][3] + b0.w);
            float4 o1 = make_float4(acc[i][4] + b1.x, acc[i][5] + b1.y,
                                    acc[i][6] + b1.z, acc[i][7] + b1.w);
            *(float4*)(g_qkv + (size_t)row * 512 + col)     = o0;
            *(float4*)(g_qkv + (size_t)row * 512 + col + 4) = o1;
        }
    }
}

// --------------------------- K2: edge compat --------------------------------
// One warp per edge. Lane j handles dims [4j, 4j+4) of the 128-dim head space.
__global__ void __launch_bounds__(256) k_edge_compat(
    const int* __restrict__ ei, const float* __restrict__ ea,
    const float* __restrict__ Wk, const float* __restrict__ bk,
    const float* __restrict__ Wq, const float* __restrict__ bq, int E)
{
    __shared__ float sWq[18 * 128];
    __shared__ float sWk[18 * 128];
    __shared__ float sbq[128];
    __shared__ float sbk[128];

    for (int i = threadIdx.x; i < 18 * 128; i += 256) {
        sWq[i] = Wq[i];
        sWk[i] = Wk[i];
    }
    if (threadIdx.x < 128) {
        sbq[threadIdx.x] = bq[threadIdx.x];
        sbk[threadIdx.x] = bk[threadIdx.x];
    }
    __syncthreads();

    int e = blockIdx.x * 8 + (threadIdx.x >> 5);
    if (e >= E) return;
    int lane = threadIdx.x & 31;

    int s = ei[e];
    int t = ei[E + e];

    float eal = (lane < 18) ? ea[(size_t)e * 18 + lane] : 0.0f;

    const int c0 = lane * 4;
    float aq0 = sbq[c0], aq1 = sbq[c0 + 1], aq2 = sbq[c0 + 2], aq3 = sbq[c0 + 3];
    float ak0 = sbk[c0], ak1 = sbk[c0 + 1], ak2 = sbk[c0 + 2], ak3 = sbk[c0 + 3];

#pragma unroll
    for (int i = 0; i < 18; i++) {
        float v = __shfl_sync(0xffffffffu, eal, i);
        const float* wq = &sWq[i * 128 + c0];
        const float* wk = &sWk[i * 128 + c0];
        aq0 += v * wq[0]; aq1 += v * wq[1]; aq2 += v * wq[2]; aq3 += v * wq[3];
        ak0 += v * wk[0]; ak1 += v * wk[1]; ak2 += v * wk[2]; ak3 += v * wk[3];
    }

    float4 q4 = *(const float4*)(g_qkv + (size_t)s * 512 + c0);
    float4 k4 = *(const float4*)(g_qkv + (size_t)t * 512 + 128 + c0);

    float p = (q4.x * SCALE + aq0) * (k4.x + ak0)
            + (q4.y * SCALE + aq1) * (k4.y + ak1)
            + (q4.z * SCALE + aq2) * (k4.z + ak2)
            + (q4.w * SCALE + aq3) * (k4.w + ak3);
    p += __shfl_xor_sync(0xffffffffu, p, 1);

    if ((lane & 1) == 0) {
        int h = lane >> 1;
        g_ex[(size_t)e * HH + h] = p;
        atomicMaxFloat(&g_max[s * HH + h], p);
    }
}

// --------------------------- K3: exp + denom -------------------------------
__global__ void __launch_bounds__(256) k_expsum(const int* __restrict__ ei, int E)
{
    int idx = blockIdx.x * blockDim.x + threadIdx.x;
    if (idx >= E * HH) return;
    int e = idx >> 4;
    int h = idx & 15;
    int s = ei[e];
    float ex = __expf(g_ex[idx] - g_max[s * HH + h]);
    g_ex[idx] = ex;
    atomicAdd(&g_sum[s * HH + h], ex);
}

// --------------------------- K4: weighted message scatter -------------------
// One warp per edge. Lane j handles out dims [8j, 8j+8) -> head j/2.
__global__ void __launch_bounds__(256) k_message(
    const int* __restrict__ ei, float* __restrict__ out, int E)
{
    int e = blockIdx.x * 8 + (threadIdx.x >> 5);
    if (e >= E) return;
    int lane = threadIdx.x & 31;

    int s = ei[e];
    int t = ei[E + e];
    int h = lane >> 1;

    float ex  = g_ex[(size_t)e * HH + h];
    float den = g_sum[s * HH + h];
    float a   = ex / (den + 1e-16f);

    const float* vp = g_qkv + (size_t)t * 512 + 256 + lane * 8;
    float4 v0 = *(const float4*)vp;
    float4 v1 = *(const float4*)(vp + 4);

    float* op = out + (size_t)s * 256 + lane * 8;
    atomicAdd(op + 0, a * v0.x);
    atomicAdd(op + 1, a * v0.y);
    atomicAdd(op + 2, a * v0.z);
    atomicAdd(op + 3, a * v0.w);
    atomicAdd(op + 4, a * v1.x);
    atomicAdd(op + 5, a * v1.y);
    atomicAdd(op + 6, a * v1.z);
    atomicAdd(op + 7, a * v1.w);
}

// ---------------------------------------------------------------------------
extern "C" void kernel_launch(void* const* d_in, const int* in_sizes, int n_in,
                              void* d_out, int out_size)
{
    const float* x    = (const float*)d_in[0];
    const int*   ei   = (const int*)d_in[1];
    const float* ea   = (const float*)d_in[2];
    const float* Wqkv = (const float*)d_in[3];
    const float* bqkv = (const float*)d_in[4];
    const float* Wk   = (const float*)d_in[5];
    const float* bk   = (const float*)d_in[6];
    const float* Wq   = (const float*)d_in[7];
    const float* bq   = (const float*)d_in[8];
    float*       out  = (float*)d_out;

    int M = in_sizes[0] / 256;   // num nodes
    int E = in_sizes[1] / 2;     // num edges

    int n_out = M * 256;
    k_init<<<(n_out + 255) / 256, 256>>>(out, n_out, M);

    dim3 g1(4, (M + 127) / 128);
    k_gemm<<<g1, 256>>>(x, Wqkv, bqkv, M);

    k_edge_compat<<<(E + 7) / 8, 256>>>(ei, ea, Wk, bk, Wq, bq, E);

    k_expsum<<<(E * HH + 255) / 256, 256>>>(ei, E);

    k_message<<<(E + 7) / 8, 256>>>(ei, out, E);
}

// round 3
// speedup vs baseline: 1.5909x; 1.5909x over previous
#include <cuda_runtime.h>

// ---------------------------------------------------------------------------
// SelfAttentionBlock: graph attention with per-edge RPE.
// N=50000, E=800000, DIM=256, H=16, D=8, DH=128, IN_RPE=18. SCALE=1/sqrt(8).
//
// Pipeline:
//   K0 init     : zero d_out, zero g_sum, set g_max = -inf
//   K1 gemm     : g_qkv = x @ Wqkv + bqkv            (N, 512)
//   K2 compat   : per-edge RPE GEMVs + q.k dot, store compat, atomicMax
//   K3 expsum   : ex = exp(compat - max[s]), store ex, atomicAdd denom
//   K4 message  : out[s] += (ex/(den[s]+eps)) * v[t]  via red.global.v4.f32.add
// ---------------------------------------------------------------------------

#define MAX_N 50000
#define MAX_E 800000
#define HH    16
#define SCALE 0.35355339059327373f   // 8^-0.5

__device__ float g_qkv[(size_t)MAX_N * 512];   // [q(128) | k(128) | v(256)]
__device__ float g_ex [(size_t)MAX_E * HH];    // compat, then exp(compat-max)
__device__ float g_max[(size_t)MAX_N * HH];
__device__ float g_sum[(size_t)MAX_N * HH];

// ---------------------------------------------------------------------------
__device__ __forceinline__ void atomicMaxFloat(float* addr, float val) {
    if (val >= 0.0f) {
        atomicMax((int*)addr, __float_as_int(val));
    } else {
        atomicMin((unsigned int*)addr, __float_as_uint(val));
    }
}

// Vectorized global reduction (sm_90+): one instruction adds 4 floats.
__device__ __forceinline__ void red_add_v4(float* addr, float a, float b,
                                           float c, float d) {
    asm volatile("red.global.v4.f32.add [%0], {%1, %2, %3, %4};"
                 :: "l"(addr), "f"(a), "f"(b), "f"(c), "f"(d)
                 : "memory");
}

// --------------------------- K0: init --------------------------------------
__global__ void k_init(float4* __restrict__ out, int n_out4, int n_nodes) {
    int i = blockIdx.x * blockDim.x + threadIdx.x;
    if (i < n_out4) out[i] = make_float4(0.f, 0.f, 0.f, 0.f);
    if (i < n_nodes * HH) {
        g_max[i] = __int_as_float(0xff800000);  // -inf
        g_sum[i] = 0.0f;
    }
}

// --------------------------- K1: qkv GEMM ----------------------------------
// C[M,512] = X[M,256] @ W[256,512] + bias ;  BM=128, BN=128, BK=8, TM=TN=8
__global__ void __launch_bounds__(256) k_gemm(
    const float* __restrict__ X, const float* __restrict__ W,
    const float* __restrict__ bias, int M)
{
    __shared__ float As[8][128];   // transposed A tile
    __shared__ float Bs[8][128];

    const int tid = threadIdx.x;
    const int tr  = tid >> 4;          // 0..15
    const int tc  = tid & 15;          // 0..15
    const int aRow = tid >> 1;         // 0..127
    const int aCol = (tid & 1) * 4;    // 0 or 4
    const int bRow = tid >> 5;         // 0..7
    const int bCol = (tid & 31) * 4;   // 0..124

    const int rowBase = blockIdx.y * 128;
    const int colBase = blockIdx.x * 128;
    const int gRow = rowBase + aRow;

    float acc[8][8];
#pragma unroll
    for (int i = 0; i < 8; i++)
#pragma unroll
        for (int j = 0; j < 8; j++) acc[i][j] = 0.0f;

    for (int k0 = 0; k0 < 256; k0 += 8) {
        float4 a4 = make_float4(0.f, 0.f, 0.f, 0.f);
        if (gRow < M)
            a4 = *(const float4*)(X + (size_t)gRow * 256 + k0 + aCol);
        As[aCol + 0][aRow] = a4.x;
        As[aCol + 1][aRow] = a4.y;
        As[aCol + 2][aRow] = a4.z;
        As[aCol + 3][aRow] = a4.w;

        *(float4*)&Bs[bRow][bCol] =
            *(const float4*)(W + (size_t)(k0 + bRow) * 512 + colBase + bCol);
        __syncthreads();

#pragma unroll
        for (int k = 0; k < 8; k++) {
            float4 a0 = *(float4*)&As[k][tr * 8];
            float4 a1 = *(float4*)&As[k][tr * 8 + 4];
            float4 b0 = *(float4*)&Bs[k][tc * 8];
            float4 b1 = *(float4*)&Bs[k][tc * 8 + 4];
            float ra[8] = {a0.x, a0.y, a0.z, a0.w, a1.x, a1.y, a1.z, a1.w};
            float rb[8] = {b0.x, b0.y, b0.z, b0.w, b1.x, b1.y, b1.z, b1.w};
#pragma unroll
            for (int i = 0; i < 8; i++)
#pragma unroll
                for (int j = 0; j < 8; j++)
                    acc[i][j] += ra[i] * rb[j];
        }
        __syncthreads();
    }

#pragma unroll
    for (int i = 0; i < 8; i++) {
        int row = rowBase + tr * 8 + i;
        if (row < M) {
            int col = colBase + tc * 8;
            float4 b0 = *(const float4*)(bias + col);
            float4 b1 = *(const float4*)(bias + col + 4);
            float4 o0 = make_float4(acc[i][0] + b0.x, acc[i][1] + b0.y,
                                    acc[i][2] + b0.z, acc[i][3] + b0.w);
            float4 o1 = make_float4(acc[i][4] + b1.x, acc[i][5] + b1.y,
                                    acc[i][6] + b1.z, acc[i][7] + b1.w);
            *(float4*)(g_qkv + (size_t)row * 512 + col)     = o0;
            *(float4*)(g_qkv + (size_t)row * 512 + col + 4) = o1;
        }
    }
}

// --------------------------- K2: edge compat --------------------------------
// One warp per edge. Lane j handles dims [4j, 4j+4) of the 128-dim head space.
__global__ void __launch_bounds__(256) k_edge_compat(
    const int* __restrict__ ei, const float* __restrict__ ea,
    const float* __restrict__ Wk, const float* __restrict__ bk,
    const float* __restrict__ Wq, const float* __restrict__ bq, int E)
{
    __shared__ float sWq[18 * 128];
    __shared__ float sWk[18 * 128];
    __shared__ float sbq[128];
    __shared__ float sbk[128];

    for (int i = threadIdx.x; i < 18 * 128; i += 256) {
        sWq[i] = Wq[i];
        sWk[i] = Wk[i];
    }
    if (threadIdx.x < 128) {
        sbq[threadIdx.x] = bq[threadIdx.x];
        sbk[threadIdx.x] = bk[threadIdx.x];
    }
    __syncthreads();

    int e = blockIdx.x * 8 + (threadIdx.x >> 5);
    if (e >= E) return;
    int lane = threadIdx.x & 31;

    int s = ei[e];
    int t = ei[E + e];

    float eal = (lane < 18) ? ea[(size_t)e * 18 + lane] : 0.0f;

    const int c0 = lane * 4;
    float aq0 = sbq[c0], aq1 = sbq[c0 + 1], aq2 = sbq[c0 + 2], aq3 = sbq[c0 + 3];
    float ak0 = sbk[c0], ak1 = sbk[c0 + 1], ak2 = sbk[c0 + 2], ak3 = sbk[c0 + 3];

#pragma unroll
    for (int i = 0; i < 18; i++) {
        float v = __shfl_sync(0xffffffffu, eal, i);
        const float* wq = &sWq[i * 128 + c0];
        const float* wk = &sWk[i * 128 + c0];
        aq0 += v * wq[0]; aq1 += v * wq[1]; aq2 += v * wq[2]; aq3 += v * wq[3];
        ak0 += v * wk[0]; ak1 += v * wk[1]; ak2 += v * wk[2]; ak3 += v * wk[3];
    }

    float4 q4 = *(const float4*)(g_qkv + (size_t)s * 512 + c0);
    float4 k4 = *(const float4*)(g_qkv + (size_t)t * 512 + 128 + c0);

    float p = (q4.x * SCALE + aq0) * (k4.x + ak0)
            + (q4.y * SCALE + aq1) * (k4.y + ak1)
            + (q4.z * SCALE + aq2) * (k4.z + ak2)
            + (q4.w * SCALE + aq3) * (k4.w + ak3);
    p += __shfl_xor_sync(0xffffffffu, p, 1);

    if ((lane & 1) == 0) {
        int h = lane >> 1;
        g_ex[(size_t)e * HH + h] = p;
        atomicMaxFloat(&g_max[s * HH + h], p);
    }
}

// --------------------------- K3: exp + denom -------------------------------
__global__ void __launch_bounds__(256) k_expsum(const int* __restrict__ ei, int E)
{
    int idx = blockIdx.x * blockDim.x + threadIdx.x;
    if (idx >= E * HH) return;
    int e = idx >> 4;
    int h = idx & 15;
    int s = ei[e];
    float ex = __expf(g_ex[idx] - g_max[s * HH + h]);
    g_ex[idx] = ex;
    atomicAdd(&g_sum[s * HH + h], ex);
}

// --------------------------- K4: weighted message scatter -------------------
// One warp per edge. Lane j handles out dims [8j, 8j+8) -> head j/2.
// Uses vectorized red.global.v4.f32.add: 2 instructions/lane instead of 8.
__global__ void __launch_bounds__(256) k_message(
    const int* __restrict__ ei, float* __restrict__ out, int E)
{
    int e = blockIdx.x * 8 + (threadIdx.x >> 5);
    if (e >= E) return;
    int lane = threadIdx.x & 31;

    int s = ei[e];
    int t = ei[E + e];
    int h = lane >> 1;

    float ex  = g_ex[(size_t)e * HH + h];
    float den = g_sum[s * HH + h];
    float a   = ex / (den + 1e-16f);

    const float* vp = g_qkv + (size_t)t * 512 + 256 + lane * 8;
    float4 v0 = *(const float4*)vp;
    float4 v1 = *(const float4*)(vp + 4);

    float* op = out + (size_t)s * 256 + lane * 8;
    red_add_v4(op,     a * v0.x, a * v0.y, a * v0.z, a * v0.w);
    red_add_v4(op + 4, a * v1.x, a * v1.y, a * v1.z, a * v1.w);
}

// ---------------------------------------------------------------------------
extern "C" void kernel_launch(void* const* d_in, const int* in_sizes, int n_in,
                              void* d_out, int out_size)
{
    const float* x    = (const float*)d_in[0];
    const int*   ei   = (const int*)d_in[1];
    const float* ea   = (const float*)d_in[2];
    const float* Wqkv = (const float*)d_in[3];
    const float* bqkv = (const float*)d_in[4];
    const float* Wk   = (const float*)d_in[5];
    const float* bk   = (const float*)d_in[6];
    const float* Wq   = (const float*)d_in[7];
    const float* bq   = (const float*)d_in[8];
    float*       out  = (float*)d_out;

    int M = in_sizes[0] / 256;   // num nodes
    int E = in_sizes[1] / 2;     // num edges

    int n_out4 = M * 64;   // M*256 floats / 4
    k_init<<<(n_out4 + 255) / 256, 256>>>((float4*)out, n_out4, M);

    dim3 g1(4, (M + 127) / 128);
    k_gemm<<<g1, 256>>>(x, Wqkv, bqkv, M);

    k_edge_compat<<<(E + 7) / 8, 256>>>(ei, ea, Wk, bk, Wq, bq, E);

    k_expsum<<<(E * HH + 255) / 256, 256>>>(ei, E);

    k_message<<<(E + 7) / 8, 256>>>(ei, out, E);
}